// round 10
// baseline (speedup 1.0000x reference)
#include <cuda_runtime.h>
#include <math.h>
#include <cub/cub.cuh>

#define BB 4
#define CC 64
#define NN 4096
#define INTER 16
#define TILE 128
#define NT (NN / TILE)    // 32
#define NBLK (BB * NT)    // 128 blocks (<=148 SMs: co-resident)
#define NTHR 256

// ---------------- scratch (device globals; no allocations allowed) ----------
__device__ float g_a[BB * NN];
__device__ double g_dd[BB * NN];
__device__ __align__(16) float g_vp[BB * NN * CC];
__device__ float g_s[BB * NN];
__device__ float g_e[BB * NN];
__device__ int   g_idx[BB * NN];
__device__ __align__(16) float g_Pva[BB * (NN + 1) * CC];
__device__ __align__(16) float g_Pv [BB * (NN + 1) * CC];
__device__ __align__(16) float g_Pve[BB * (NN + 1) * CC];
__device__ double g_Pa[BB * (NN + 1)];
__device__ double g_Pe[BB * (NN + 1)];
// decoupled-lookback state: 0=invalid, 1=aggregate ready, 2=prefix ready
__device__ int   g_state[NBLK];
__device__ float g_agg [NBLK * 3 * CC];
__device__ float g_pref[NBLK * 3 * CC];
// grid barrier
__device__ int g_bar_count;
__device__ int g_bar_gen;

__device__ __forceinline__ void grid_barrier() {
    __syncthreads();
    if (threadIdx.x == 0) {
        __threadfence();
        int gen = *((volatile int*)&g_bar_gen);          // snapshot BEFORE arrive
        if (atomicAdd(&g_bar_count, 1) == NBLK - 1) {
            g_bar_count = 0;
            __threadfence();
            atomicAdd(&g_bar_gen, 1);                    // release
        } else {
            while (*((volatile int*)&g_bar_gen) == gen) __nanosleep(64);
        }
        __threadfence();
    }
    __syncthreads();
}

typedef cub::BlockRadixSort<float, NTHR, 16, int> Sorter;

struct PhaseA {
    float W[CC * CC];
    double wa[CC], wd[CC];
    float b[CC];
    double ca, cd;
};
struct PhaseC {
    float s_s[TILE], s_e[TILE];
    int s_idx[TILE];
    float partial[3 * 4 * CC];
    float off[3 * CC];
};
struct PhaseD {
    float Pva[32 * 65], Pv[32 * 65], Pve[32 * 65];
    float tva[CC], tv[CC], bgv[CC];
    float inv[32], dj[32], ed[32];
    int r[32];
};

__host__ __device__ constexpr size_t cmax2(size_t a, size_t b) { return a > b ? a : b; }
constexpr size_t SMEM_BYTES =
    cmax2(sizeof(PhaseA),
    cmax2(sizeof(typename Sorter::TempStorage),
    cmax2(2 * NTHR * sizeof(double),
    cmax2(sizeof(PhaseC), sizeof(PhaseD)))));

__global__ void __launch_bounds__(NTHR, 1) k_all(
        const float* __restrict__ x,
        const float* __restrict__ Wq, const float* __restrict__ bq,
        const float* __restrict__ Wk, const float* __restrict__ bk,
        const float* __restrict__ wcq, const float* __restrict__ wck,
        const float* __restrict__ Wv, const float* __restrict__ bv,
        const float* __restrict__ Wg, const float* __restrict__ bg,
        float* __restrict__ out) {
    __shared__ __align__(128) char smem_raw[SMEM_BYTES];
    int blk = blockIdx.x;
    int tid = threadIdx.x;

    // ================= Phase A: fold weights + projections =================
    if (blk < 64) {
        PhaseA& sa = *(PhaseA*)smem_raw;
        for (int e = tid; e < CC * CC; e += NTHR) {
            int cin = e / CC, o = e % CC;
            float s = 0.f;
            for (int m = 0; m < CC; m++) s += Wg[o * CC + m] * Wv[m * CC + cin];
            sa.W[cin * CC + o] = s;
        }
        if (tid < CC) {
            double swa = 0.0, swd = 0.0;
            for (int i = 0; i < INTER; i++) {
                swa += (double)wcq[i] * (double)Wq[i * CC + tid];
                swd += (double)wck[i] * (double)Wk[i * CC + tid];
            }
            sa.wa[tid] = swa;
            sa.wd[tid] = swd;
            float s = 0.f;
            for (int m = 0; m < CC; m++) s += Wg[tid * CC + m] * bv[m];
            sa.b[tid] = s;
        }
        if (tid == 0) {
            double ca = 0.0, cd = 0.0;
            for (int i = 0; i < INTER; i++) {
                ca += (double)wcq[i] * (double)bq[i];
                cd += (double)wck[i] * (double)bk[i];
            }
            sa.ca = ca;
            sa.cd = cd;
        }
        __syncthreads();

        int g = blk * NTHR + tid;       // 0 .. B*N-1 (64*256 = 16384)
        int b = g / NN, n = g % NN;
        const float* xb = x + (size_t)b * CC * NN + n;

        float acc[CC];
#pragma unroll
        for (int o = 0; o < CC; o++) acc[o] = sa.b[o];
        double aa = sa.ca, dd = sa.cd;

        for (int cin = 0; cin < CC; cin++) {
            float xv = xb[(size_t)cin * NN];
            aa += sa.wa[cin] * (double)xv;
            dd += sa.wd[cin] * (double)xv;
            const float4* wrow = (const float4*)&sa.W[cin * CC];
#pragma unroll
            for (int o4 = 0; o4 < CC / 4; o4++) {
                float4 w = wrow[o4];
                acc[o4 * 4 + 0] += w.x * xv;
                acc[o4 * 4 + 1] += w.y * xv;
                acc[o4 * 4 + 2] += w.z * xv;
                acc[o4 * 4 + 3] += w.w * xv;
            }
        }
        g_a[g] = (float)aa;
        g_dd[g] = dd;
        float4* vout = (float4*)&g_vp[(size_t)g * CC];
#pragma unroll
        for (int o4 = 0; o4 < CC / 4; o4++)
            vout[o4] = make_float4(acc[o4 * 4 + 0], acc[o4 * 4 + 1], acc[o4 * 4 + 2], acc[o4 * 4 + 3]);
    } else if (blk == 64) {
        // zero lookback states + prefix row 0
        for (int i = tid; i < NBLK; i += NTHR) g_state[i] = 0;
        for (int i = tid; i < BB * CC; i += NTHR) {
            int b = i / CC, c = i % CC;
            size_t p0 = ((size_t)b * (NN + 1)) * CC + c;
            g_Pva[p0] = 0.f; g_Pv[p0] = 0.f; g_Pve[p0] = 0.f;
        }
    }
    grid_barrier();

    // ================= Phase B: sort + exp + fp64 Pa/Pe scan ===============
    if (blk < BB) {
        int b = blk;
        {
            typename Sorter::TempStorage& st = *(typename Sorter::TempStorage*)smem_raw;
            float keys[16];
            int vals[16];
#pragma unroll
            for (int u = 0; u < 16; u++) {
                int r = 16 * tid + u;
                keys[u] = g_a[b * NN + r];
                vals[u] = r;
            }
            Sorter(st).Sort(keys, vals);   // ascending, blocked

            float ev[16];
            double l0 = 0.0, l1 = 0.0;
#pragma unroll
            for (int u = 0; u < 16; u++) {
                int r = 16 * tid + u;
                ev[u] = expf(keys[u]);
                g_s[b * NN + r]   = keys[u];
                g_idx[b * NN + r] = vals[u];
                g_e[b * NN + r]   = ev[u];
                l0 += (double)keys[u];
                l1 += (double)ev[u];
            }
            __syncthreads();   // done with sort smem

            double* red = (double*)smem_raw;
            red[tid] = l0;
            red[NTHR + tid] = l1;
            __syncthreads();
            for (int off = 1; off < NTHR; off <<= 1) {
                double t0 = 0, t1 = 0;
                if (tid >= off) { t0 = red[tid - off]; t1 = red[NTHR + tid - off]; }
                __syncthreads();
                red[tid] += t0;
                red[NTHR + tid] += t1;
                __syncthreads();
            }
            double b0 = 0, b1 = 0;
            if (tid > 0) { b0 = red[tid - 1]; b1 = red[NTHR + tid - 1]; }

            size_t base = (size_t)b * (NN + 1);
            if (tid == 0) { g_Pa[base] = 0.0; g_Pe[base] = 0.0; }
            double r0d = b0, r1d = b1;
#pragma unroll
            for (int u = 0; u < 16; u++) {
                int r = 16 * tid + u;
                r0d += (double)keys[u];
                r1d += (double)ev[u];
                g_Pa[base + r + 1] = r0d;
                g_Pe[base + r + 1] = r1d;
            }
        }
    }
    grid_barrier();

    // ================= Phase C: decoupled-lookback channel prefix scan =====
    {
        PhaseC& sc = *(PhaseC*)smem_raw;
        int b = blk / NT, tile = blk % NT;
        int c = tid & 63, q = tid >> 6;
        int rloc = q * 32;
        int rglob = tile * TILE;

        for (int i = tid; i < TILE; i += NTHR) {
            sc.s_s[i]   = g_s[b * NN + rglob + i];
            sc.s_e[i]   = g_e[b * NN + rglob + i];
            sc.s_idx[i] = g_idx[b * NN + rglob + i];
        }
        __syncthreads();

        const float* vp = &g_vp[((size_t)b * NN) * CC];
        float fv[32];
#pragma unroll
        for (int k = 0; k < 32; k++)
            fv[k] = vp[(size_t)sc.s_idx[rloc + k] * CC + c];
        float s0 = 0.f, s1 = 0.f, s2 = 0.f;
#pragma unroll
        for (int k = 0; k < 32; k++) {
            float f = fv[k];
            s0 += f * sc.s_s[rloc + k];
            s1 += f;
            s2 += f * sc.s_e[rloc + k];
        }
        sc.partial[(0 * 4 + q) * CC + c] = s0;
        sc.partial[(1 * 4 + q) * CC + c] = s1;
        sc.partial[(2 * 4 + q) * CC + c] = s2;
        __syncthreads();

        float a0 = 0.f, a1 = 0.f, a2 = 0.f;
        if (tid < CC) {
            a0 = sc.partial[(0*4+0)*CC+tid] + sc.partial[(0*4+1)*CC+tid] + sc.partial[(0*4+2)*CC+tid] + sc.partial[(0*4+3)*CC+tid];
            a1 = sc.partial[(1*4+0)*CC+tid] + sc.partial[(1*4+1)*CC+tid] + sc.partial[(1*4+2)*CC+tid] + sc.partial[(1*4+3)*CC+tid];
            a2 = sc.partial[(2*4+0)*CC+tid] + sc.partial[(2*4+1)*CC+tid] + sc.partial[(2*4+2)*CC+tid] + sc.partial[(2*4+3)*CC+tid];
            size_t ob = (size_t)blk * 3 * CC + tid;
            if (tile == 0) {
                g_pref[ob + 0 * CC] = a0;
                g_pref[ob + 1 * CC] = a1;
                g_pref[ob + 2 * CC] = a2;
            } else {
                g_agg[ob + 0 * CC] = a0;
                g_agg[ob + 1 * CC] = a1;
                g_agg[ob + 2 * CC] = a2;
            }
        }
        __syncthreads();
        __threadfence();
        if (tid == 0) *((volatile int*)&g_state[blk]) = (tile == 0) ? 2 : 1;

        double o0 = 0.0, o1 = 0.0, o2 = 0.0;
        if (tile > 0 && tid < CC) {
            volatile float* vagg  = (volatile float*)g_agg;
            volatile float* vpref = (volatile float*)g_pref;
            int p = blk - 1;
            while (true) {
                int st;
                do { st = *((volatile int*)&g_state[p]); } while (st == 0);
                size_t pb = (size_t)p * 3 * CC + tid;
                if (st == 2) {
                    o0 += (double)vpref[pb + 0 * CC];
                    o1 += (double)vpref[pb + 1 * CC];
                    o2 += (double)vpref[pb + 2 * CC];
                    break;
                } else {
                    o0 += (double)vagg[pb + 0 * CC];
                    o1 += (double)vagg[pb + 1 * CC];
                    o2 += (double)vagg[pb + 2 * CC];
                    p--;
                }
            }
            size_t ob = (size_t)blk * 3 * CC + tid;
            g_pref[ob + 0 * CC] = (float)(o0 + (double)a0);
            g_pref[ob + 1 * CC] = (float)(o1 + (double)a1);
            g_pref[ob + 2 * CC] = (float)(o2 + (double)a2);
        }
        if (tile > 0) {
            __syncthreads();
            __threadfence();
            if (tid == 0) *((volatile int*)&g_state[blk]) = 2;
        }
        if (tid < CC) {
            sc.off[0 * CC + tid] = (float)o0;
            sc.off[1 * CC + tid] = (float)o1;
            sc.off[2 * CC + tid] = (float)o2;
        }
        __syncthreads();

        float r0 = sc.off[0 * CC + c], r1 = sc.off[1 * CC + c], r2 = sc.off[2 * CC + c];
#pragma unroll
        for (int qq = 0; qq < 3; qq++) {
            if (qq < q) {
                r0 += sc.partial[(0 * 4 + qq) * CC + c];
                r1 += sc.partial[(1 * 4 + qq) * CC + c];
                r2 += sc.partial[(2 * 4 + qq) * CC + c];
            }
        }

        size_t pbase = ((size_t)b * (NN + 1)) * CC + c;
#pragma unroll 4
        for (int k = 0; k < 32; k++) {
            float f = fv[k];
            r0 += f * sc.s_s[rloc + k];
            r1 += f;
            r2 += f * sc.s_e[rloc + k];
            size_t o = pbase + (size_t)(rglob + rloc + k + 1) * CC;
            g_Pva[o] = r0;
            g_Pv[o]  = r1;
            g_Pve[o] = r2;
        }
    }
    grid_barrier();

    // ================= Phase D: per-column output ==========================
    {
        PhaseD& sd = *(PhaseD*)smem_raw;
        int b = blk >> 5;                  // 4 batches * 32 blocks
        int jb0 = (blk & 31) * 128;        // 128 columns per block
        if (tid < CC) {
            size_t totrow = ((size_t)b * (NN + 1) + NN) * CC;
            sd.tva[tid] = g_Pva[totrow + tid];
            sd.tv[tid]  = g_Pv[totrow + tid];
            sd.bgv[tid] = bg[tid];
        }
        __syncthreads();

        for (int g4 = 0; g4 < 4; g4++) {
            int jbase = jb0 + g4 * 32;
            if (tid < 32) {
                int j = jbase + tid;
                double djd = g_dd[b * NN + j];
                float t = (float)(-djd);
                const float* s = &g_s[b * NN];
                int lo = 0, hi = NN;
                while (lo < hi) {
                    int mid = (lo + hi) >> 1;
                    if (s[mid] <= t) lo = mid + 1; else hi = mid;
                }
                int r = lo;
                double edd = exp(djd);
                size_t sbase = (size_t)b * (NN + 1);
                double SaN = g_Pa[sbase + NN];
                double S = (SaN - g_Pa[sbase + r]) + (double)(NN - r) * djd
                         + edd * g_Pe[sbase + r] - (double)r;
                sd.inv[tid] = (float)(1.0 / (1.5 * S));
                sd.dj[tid] = (float)djd;
                sd.ed[tid] = (float)edd;
                sd.r[tid] = r;
            }
            __syncthreads();

            for (int e = tid; e < 32 * CC; e += NTHR) {
                int row = e >> 6, col = e & 63;
                size_t ro = ((size_t)b * (NN + 1) + sd.r[row]) * CC + col;
                sd.Pva[row * 65 + col] = g_Pva[ro];
                sd.Pv[row * 65 + col]  = g_Pv[ro];
                sd.Pve[row * 65 + col] = g_Pve[ro];
            }
            __syncthreads();

            int j = tid & 31;
            int cg = tid >> 5;
            float dj = sd.dj[j], ed = sd.ed[j], inv = sd.inv[j];
            float* ob = out + (size_t)b * CC * NN + jbase + j;
#pragma unroll
            for (int u = 0; u < 8; u++) {
                int c = cg * 8 + u;
                float pva = sd.Pva[j * 65 + c];
                float pv  = sd.Pv[j * 65 + c];
                float pve = sd.Pve[j * 65 + c];
                float num = (sd.tva[c] - pva) + dj * (sd.tv[c] - pv) + ed * pve - pv;
                ob[(size_t)c * NN] = inv * num + sd.bgv[c];
            }
            __syncthreads();
        }
    }
}

// ---------------- launcher ----------------------------------------------
extern "C" void kernel_launch(void* const* d_in, const int* in_sizes, int n_in,
                              void* d_out, int out_size) {
    const float* x   = (const float*)d_in[0];
    const float* Wq  = (const float*)d_in[1];
    const float* bq  = (const float*)d_in[2];
    const float* Wk  = (const float*)d_in[3];
    const float* bk  = (const float*)d_in[4];
    const float* wcq = (const float*)d_in[5];
    const float* wck = (const float*)d_in[6];
    const float* Wv  = (const float*)d_in[7];
    const float* bv  = (const float*)d_in[8];
    const float* Wg  = (const float*)d_in[9];
    const float* bg  = (const float*)d_in[10];
    float* out = (float*)d_out;

    k_all<<<NBLK, NTHR>>>(x, Wq, bq, Wk, bk, wcq, wck, Wv, bv, Wg, bg, out);
}